// round 6
// baseline (speedup 1.0000x reference)
#include <cuda_runtime.h>
#include <cstdint>
#include <cstddef>

#define NORB   9
#define NATOMS 384
#define NEDGES 6144
#define NKP    4
#define ALLN   (NATOMS * NORB)              // 3456
#define NFEAT  58
#define NCPLX  ((size_t)NKP * ALLN * ALLN)  // 47,775,744 = 4*3456*3456
#define NQ     4                            // column quarters
#define QATOMS (NATOMS / NQ)                // 96 atoms per quarter
#define QCOLS  (QATOMS * NORB)              // 864 columns per quarter

// Static feature -> (row, col, factor) maps for upper-tri orbital pairs
// l = [0,1,2], dims = [1,3,5], offsets = [0,1,4]
__constant__ unsigned char cROWS[NFEAT] = {
    0,
    0,0,0,
    0,0,0,0,0,
    1,1,1,2,2,2,3,3,3,
    1,1,1,1,1,2,2,2,2,2,3,3,3,3,3,
    4,4,4,4,4,5,5,5,5,5,6,6,6,6,6,7,7,7,7,7,8,8,8,8,8
};
__constant__ unsigned char cCOLS[NFEAT] = {
    0,
    1,2,3,
    4,5,6,7,8,
    1,2,3,1,2,3,1,2,3,
    4,5,6,7,8,4,5,6,7,8,4,5,6,7,8,
    4,5,6,7,8,4,5,6,7,8,4,5,6,7,8,4,5,6,7,8,4,5,6,7,8
};
__constant__ float cFACS[NFEAT] = {
    0.5f,
    1.f,1.f,1.f,
    1.f,1.f,1.f,1.f,1.f,
    0.5f,0.5f,0.5f,0.5f,0.5f,0.5f,0.5f,0.5f,0.5f,
    1.f,1.f,1.f,1.f,1.f,1.f,1.f,1.f,1.f,1.f,1.f,1.f,1.f,1.f,1.f,
    0.5f,0.5f,0.5f,0.5f,0.5f,0.5f,0.5f,0.5f,0.5f,0.5f,0.5f,0.5f,0.5f,
    0.5f,0.5f,0.5f,0.5f,0.5f,0.5f,0.5f,0.5f,0.5f,0.5f,0.5f,0.5f
};

// ---- CSR scratch (device globals: no allocation) ----
__device__ int g_cnt_out[NATOMS], g_cnt_in[NATOMS];
__device__ int g_off_out[NATOMS + 1], g_off_in[NATOMS + 1];
__device__ int g_cur_out[NATOMS], g_cur_in[NATOMS];
__device__ int g_list_out[NEDGES], g_list_in[NEDGES];

__global__ void prep_zero() {
    int t = threadIdx.x;
    if (t < NATOMS) { g_cnt_out[t] = 0; g_cnt_in[t] = 0; }
}

__global__ void prep_count(const int* __restrict__ eidx) {
    int e = blockIdx.x * blockDim.x + threadIdx.x;
    if (e >= NEDGES) return;
    int i = eidx[e], j = eidx[NEDGES + e];
    if ((unsigned)i < NATOMS) atomicAdd(&g_cnt_out[i], 1);
    if ((unsigned)j < NATOMS) atomicAdd(&g_cnt_in[j], 1);
}

// One block of NATOMS threads: exclusive scan of both count arrays.
__global__ void prep_scan() {
    __shared__ int s[NATOMS];
    int t = threadIdx.x;

    // --- out ---
    s[t] = g_cnt_out[t];
    __syncthreads();
    for (int off = 1; off < NATOMS; off <<= 1) {
        int v = (t >= off) ? s[t - off] : 0;
        __syncthreads();
        s[t] += v;
        __syncthreads();
    }
    g_off_out[t + 1] = s[t];
    int excl = (t == 0) ? 0 : s[t - 1];
    if (t == 0) g_off_out[0] = 0;
    g_cur_out[t] = excl;
    __syncthreads();

    // --- in ---
    s[t] = g_cnt_in[t];
    __syncthreads();
    for (int off = 1; off < NATOMS; off <<= 1) {
        int v = (t >= off) ? s[t - off] : 0;
        __syncthreads();
        s[t] += v;
        __syncthreads();
    }
    g_off_in[t + 1] = s[t];
    excl = (t == 0) ? 0 : s[t - 1];
    if (t == 0) g_off_in[0] = 0;
    g_cur_in[t] = excl;
}

__global__ void prep_fill(const int* __restrict__ eidx) {
    int e = blockIdx.x * blockDim.x + threadIdx.x;
    if (e >= NEDGES) return;
    int i = eidx[e], j = eidx[NEDGES + e];
    if ((unsigned)i < NATOMS) g_list_out[atomicAdd(&g_cur_out[i], 1)] = e;
    if ((unsigned)j < NATOMS) g_list_in [atomicAdd(&g_cur_in [j], 1)] = e;
}

// ---- Main gather kernel ----
// CTA = (ai, k, q): owns output rows [ai*9, ai*9+9), cols [q*864, (q+1)*864)
// for kpoint k. Accumulates sparse contributions into a 31 KB smem tile,
// then streams the tile to GMEM with 128-bit stores. Every output element
// is written exactly once by exactly one CTA -> no global atomics, no
// separate zero-fill pass.
__global__ __launch_bounds__(256) void hr2hk_gather(
    const float* __restrict__ hop,     // [E, 58]
    const float* __restrict__ ons,     // [N, 58]
    const float* __restrict__ kpts,    // [4, 3]
    const int*   __restrict__ eidx,    // [2, E]
    const int*   __restrict__ eshift,  // [E, 3]
    float*       __restrict__ out)     // [4, 3456, 3456] float32 (real part)
{
    __shared__ float tile[NORB * QCOLS];   // 9 x 864 = 31,104 bytes

    const int b  = blockIdx.x;
    const int q  = b & 3;
    const int k  = (b >> 2) & 3;
    const int ai = b >> 4;
    const int tid = threadIdx.x;
    const int cbase = q * QATOMS;          // first atom column in this quarter

    // Zero the tile (float4).
    float4* t4 = (float4*)tile;
    #pragma unroll
    for (int i = tid; i < NORB * QCOLS / 4; i += 256)
        t4[i] = make_float4(0.f, 0.f, 0.f, 0.f);
    __syncthreads();

    const float kx = kpts[k * 3 + 0];
    const float ky = kpts[k * 3 + 1];
    const float kz = kpts[k * 3 + 2];

    // Onsite block (ai, ai): only if ai's columns fall in this quarter.
    if (ai >= cbase && ai < cbase + QATOMS && tid < NFEAT) {
        const int f = tid;
        const float v = cFACS[f] * ons[(size_t)ai * NFEAT + f];
        const int ro = cROWS[f], co = cCOLS[f];
        const int cc = (ai - cbase) * NORB;
        atomicAdd(&tile[ro * QCOLS + cc + co], v);   // B
        atomicAdd(&tile[co * QCOLS + cc + ro], v);   // B^T
    }

    // Out-edges of ai (i == ai): B contribution at rows ai, cols aj.
    {
        const int p0 = g_off_out[ai], p1 = g_off_out[ai + 1];
        for (int p = p0 + tid; p < p1; p += 256) {
            const int e  = g_list_out[p];
            const int aj = eidx[NEDGES + e];
            if (aj < cbase || aj >= cbase + QATOMS) continue;
            const float d = kx * (float)eshift[e * 3 + 0]
                          + ky * (float)eshift[e * 3 + 1]
                          + kz * (float)eshift[e * 3 + 2];
            const float ph = __cosf(6.283185307179586f * d);  // Re(phase)
            const float* __restrict__ src = hop + (size_t)e * NFEAT;
            const int cc = (aj - cbase) * NORB;
            #pragma unroll 8
            for (int f = 0; f < NFEAT; ++f) {
                const float v = cFACS[f] * src[f] * ph;
                atomicAdd(&tile[(int)cROWS[f] * QCOLS + cc + (int)cCOLS[f]], v);
            }
        }
    }

    // In-edges of ai (j == ai): B^H contribution at rows ai, cols src_atom
    // (real part: same cos factor, transposed orbital position).
    {
        const int p0 = g_off_in[ai], p1 = g_off_in[ai + 1];
        for (int p = p0 + tid; p < p1; p += 256) {
            const int e  = g_list_in[p];
            const int as = eidx[e];
            if (as < cbase || as >= cbase + QATOMS) continue;
            const float d = kx * (float)eshift[e * 3 + 0]
                          + ky * (float)eshift[e * 3 + 1]
                          + kz * (float)eshift[e * 3 + 2];
            const float ph = __cosf(6.283185307179586f * d);
            const float* __restrict__ src = hop + (size_t)e * NFEAT;
            const int cc = (as - cbase) * NORB;
            #pragma unroll 8
            for (int f = 0; f < NFEAT; ++f) {
                const float v = cFACS[f] * src[f] * ph;
                atomicAdd(&tile[(int)cCOLS[f] * QCOLS + cc + (int)cROWS[f]], v);
            }
        }
    }

    __syncthreads();

    // Stream the tile to GMEM: row r -> out[k][ai*9 + r][q*864 ...], float4.
    const size_t kbase = (size_t)k * ALLN * ALLN;
    float* __restrict__ obase = out + kbase + (size_t)(ai * NORB) * ALLN + q * QCOLS;
    #pragma unroll
    for (int i = tid; i < NORB * QCOLS / 4; i += 256) {
        const int r  = i / (QCOLS / 4);
        const int c4 = i % (QCOLS / 4);
        ((float4*)(obase + (size_t)r * ALLN))[c4] = t4[i];
    }
}

// ---- complex64 fallback path (kept for safety; not used when out is f32) ----
__global__ __launch_bounds__(256, 8) void hr2hk_scatter_cplx(
    const float* __restrict__ hop,
    const float* __restrict__ ons,
    const float* __restrict__ kpts,
    const int*   __restrict__ eidx,
    const int*   __restrict__ eshift,
    float*       __restrict__ out)
{
    const int w = blockIdx.x;
    const int t = threadIdx.x;
    if (t >= NFEAT * NKP) return;
    const int f = t >> 2;
    const int k = t & 3;
    const bool is_edge = (w < NEDGES);

    int ai, aj;
    float pre, pim;
    if (is_edge) {
        ai = eidx[w];
        aj = eidx[NEDGES + w];
        const float d = kpts[k * 3 + 0] * (float)eshift[w * 3 + 0]
                      + kpts[k * 3 + 1] * (float)eshift[w * 3 + 1]
                      + kpts[k * 3 + 2] * (float)eshift[w * 3 + 2];
        float s, c;
        __sincosf(6.283185307179586f * d, &s, &c);
        pre = c; pim = -s;
    } else {
        ai = w - NEDGES; aj = ai; pre = 1.f; pim = 0.f;
    }
    if ((unsigned)ai >= NATOMS || (unsigned)aj >= NATOMS) return;

    const float* __restrict__ src =
        is_edge ? (hop + (size_t)w * NFEAT)
                : (ons + (size_t)(w - NEDGES) * NFEAT);
    const float val = cFACS[f] * src[f];
    const float re = val * pre, im = val * pim;
    const int r = ai * NORB + (int)cROWS[f];
    const int c = aj * NORB + (int)cCOLS[f];
    const size_t kbase = (size_t)k * ALLN * ALLN;
    float* p0 = out + 2 * (kbase + (size_t)r * ALLN + c);
    float* p1 = out + 2 * (kbase + (size_t)c * ALLN + r);
    atomicAdd(p0 + 0, re);
    atomicAdd(p0 + 1, im);
    atomicAdd(p1 + 0, re);
    atomicAdd(p1 + 1, -im);
}

__global__ void hr2hk_zero(uint4* __restrict__ out, size_t n_u4) {
    for (size_t i = (size_t)blockIdx.x * blockDim.x + threadIdx.x;
         i < n_u4; i += (size_t)gridDim.x * blockDim.x)
        out[i] = make_uint4(0u, 0u, 0u, 0u);
}

extern "C" void kernel_launch(void* const* d_in, const int* in_sizes, int n_in,
                              void* d_out, int out_size) {
    // Identify inputs by (pairwise-distinct) element counts, not position.
    const float* hop    = nullptr;
    const float* ons    = nullptr;
    const float* kpts   = nullptr;
    const int*   eidx   = nullptr;
    const int*   eshift = nullptr;

    for (int i = 0; i < n_in; ++i) {
        switch (in_sizes[i]) {
            case NEDGES * NFEAT: hop    = (const float*)d_in[i]; break;  // 356352
            case NATOMS * NFEAT: ons    = (const float*)d_in[i]; break;  // 22272
            case NKP * 3:        kpts   = (const float*)d_in[i]; break;  // 12
            case 2 * NEDGES:     eidx   = (const int*)d_in[i];   break;  // 12288
            case NEDGES * 3:     eshift = (const int*)d_in[i];   break;  // 18432
            default: break;
        }
    }
    if (!hop || !ons || !kpts || !eidx || !eshift) return;

    if ((long long)out_size == (long long)NCPLX) {
        // float32 real-part output: single-pass gather, no global atomics.
        prep_zero<<<1, NATOMS>>>();
        prep_count<<<(NEDGES + 255) / 256, 256>>>(eidx);
        prep_scan<<<1, NATOMS>>>();
        prep_fill<<<(NEDGES + 255) / 256, 256>>>(eidx);
        hr2hk_gather<<<NATOMS * NKP * NQ, 256>>>(
            hop, ons, kpts, eidx, eshift, (float*)d_out);
    } else if ((long long)out_size == 2LL * (long long)NCPLX) {
        hr2hk_zero<<<8192, 256>>>((uint4*)d_out, NCPLX * 8 / 16);
        hr2hk_scatter_cplx<<<NEDGES + NATOMS, 256>>>(
            hop, ons, kpts, eidx, eshift, (float*)d_out);
    }
}

// round 7
// speedup vs baseline: 1.6456x; 1.6456x over previous
#include <cuda_runtime.h>
#include <cstdint>
#include <cstddef>

#define NORB   9
#define NATOMS 384
#define NEDGES 6144
#define NKP    4
#define ALLN   (NATOMS * NORB)              // 3456
#define NFEAT  58
#define NCPLX  ((size_t)NKP * ALLN * ALLN)  // 47,775,744 = 4*3456*3456
#define CAP    96                           // max edges per atom per direction
#define MAXENT (2 * CAP + 2)
#define ZBYTES 20736                        // slab(124416 B) / 6
#define TWO_PI 6.283185307179586f

// Static feature -> (row, col, factor) maps for upper-tri orbital pairs
// l = [0,1,2], dims = [1,3,5], offsets = [0,1,4]
__constant__ unsigned char cROWS[NFEAT] = {
    0,
    0,0,0,
    0,0,0,0,0,
    1,1,1,2,2,2,3,3,3,
    1,1,1,1,1,2,2,2,2,2,3,3,3,3,3,
    4,4,4,4,4,5,5,5,5,5,6,6,6,6,6,7,7,7,7,7,8,8,8,8,8
};
__constant__ unsigned char cCOLS[NFEAT] = {
    0,
    1,2,3,
    4,5,6,7,8,
    1,2,3,1,2,3,1,2,3,
    4,5,6,7,8,4,5,6,7,8,4,5,6,7,8,
    4,5,6,7,8,4,5,6,7,8,4,5,6,7,8,4,5,6,7,8,4,5,6,7,8
};
__constant__ float cFACS[NFEAT] = {
    0.5f,
    1.f,1.f,1.f,
    1.f,1.f,1.f,1.f,1.f,
    0.5f,0.5f,0.5f,0.5f,0.5f,0.5f,0.5f,0.5f,0.5f,
    1.f,1.f,1.f,1.f,1.f,1.f,1.f,1.f,1.f,1.f,1.f,1.f,1.f,1.f,1.f,
    0.5f,0.5f,0.5f,0.5f,0.5f,0.5f,0.5f,0.5f,0.5f,0.5f,0.5f,0.5f,0.5f,
    0.5f,0.5f,0.5f,0.5f,0.5f,0.5f,0.5f,0.5f,0.5f,0.5f,0.5f,0.5f
};

// ---- per-atom edge buckets (device globals: no allocation) ----
__device__ int g_cnt[2 * NATOMS];            // [0..383] out, [384..767] in
__device__ int g_bkt_out[NATOMS * CAP];
__device__ int g_bkt_in [NATOMS * CAP];

__global__ void prep_zero() {
    int t = blockIdx.x * blockDim.x + threadIdx.x;
    if (t < 2 * NATOMS) g_cnt[t] = 0;
}

__global__ void prep_fill(const int* __restrict__ eidx) {
    int e = blockIdx.x * blockDim.x + threadIdx.x;
    if (e >= NEDGES) return;
    int i = eidx[e], j = eidx[NEDGES + e];
    if ((unsigned)i < NATOMS) {
        int p = atomicAdd(&g_cnt[i], 1);
        if (p < CAP) g_bkt_out[i * CAP + p] = e;
    }
    if ((unsigned)j < NATOMS) {
        int p = atomicAdd(&g_cnt[NATOMS + j], 1);
        if (p < CAP) g_bkt_in[j * CAP + p] = e;
    }
}

__device__ __forceinline__ uint32_t smem_u32(const void* p) {
    uint32_t a;
    asm("{ .reg .u64 t; cvta.to.shared.u64 t, %1; cvt.u32.u64 %0, t; }"
        : "=r"(a) : "l"(p));
    return a;
}

// ---- Fused fill+accumulate kernel ----
// CTA = (ai, k) exclusively owns the contiguous 124,416-byte output slab
// out[k][ai*9 .. ai*9+9][*]. Zeros it with 6 TMA bulk stores replicating a
// 20.7 KB smem zero buffer (LSU-free fill), then accumulates its sparse
// edge/onsite contributions with global atomics -- safe because the slab is
// CTA-private and the TMA writes are completed (wait_group 0 + barrier)
// before any RED touches them.
__global__ __launch_bounds__(256) void hr2hk_fused(
    const float* __restrict__ hop,     // [E, 58]
    const float* __restrict__ ons,     // [N, 58]
    const float* __restrict__ kpts,    // [4, 3]
    const int*   __restrict__ eidx,    // [2, E]
    const int*   __restrict__ eshift,  // [E, 3]
    float*       __restrict__ out)     // [4, 3456, 3456] float32 (real part)
{
    __shared__ __align__(16) float zbuf[ZBYTES / 4];
    __shared__ int           sEid[MAXENT];
    __shared__ int           sCol[MAXENT];
    __shared__ float         sPh [MAXENT];
    __shared__ unsigned char sTr [MAXENT];

    const int b   = blockIdx.x;
    const int k   = b & 3;
    const int ai  = b >> 2;
    const int tid = threadIdx.x;

    const float kx = kpts[k * 3 + 0];
    const float ky = kpts[k * 3 + 1];
    const float kz = kpts[k * 3 + 2];

    const int nOut = min(g_cnt[ai], CAP);
    const int nIn  = min(g_cnt[NATOMS + ai], CAP);

    // Zero the smem replication buffer.
    float4* z4 = (float4*)zbuf;
    #pragma unroll
    for (int i = tid; i < ZBYTES / 16; i += 256)
        z4[i] = make_float4(0.f, 0.f, 0.f, 0.f);

    // Build the entry list (deterministic slots, no smem atomics).
    for (int p = tid; p < nOut; p += 256) {      // B at (rows ai, cols aj)
        const int e  = g_bkt_out[ai * CAP + p];
        const int aj = eidx[NEDGES + e];
        const float d = kx * (float)eshift[e * 3 + 0]
                      + ky * (float)eshift[e * 3 + 1]
                      + kz * (float)eshift[e * 3 + 2];
        sEid[p] = e; sCol[p] = aj * NORB;
        sPh[p] = __cosf(TWO_PI * d); sTr[p] = 0;
    }
    for (int p = tid; p < nIn; p += 256) {       // B^H at (rows ai, cols asrc)
        const int e  = g_bkt_in[ai * CAP + p];
        const int as = eidx[e];
        const float d = kx * (float)eshift[e * 3 + 0]
                      + ky * (float)eshift[e * 3 + 1]
                      + kz * (float)eshift[e * 3 + 2];
        const int q = nOut + p;
        sEid[q] = e; sCol[q] = as * NORB;
        sPh[q] = __cosf(TWO_PI * d); sTr[q] = 1;
    }
    if (tid == 0) {                              // onsite: block + transpose
        const int q = nOut + nIn;
        sEid[q]     = -1; sCol[q]     = ai * NORB; sPh[q]     = 1.f; sTr[q]     = 0;
        sEid[q + 1] = -1; sCol[q + 1] = ai * NORB; sPh[q + 1] = 1.f; sTr[q + 1] = 1;
    }
    __syncthreads();

    // TMA bulk zero-fill of the contiguous slab (6 x 20736 B = 124416 B).
    float* __restrict__ slab =
        out + (size_t)k * ALLN * ALLN + (size_t)(ai * NORB) * ALLN;
    if (tid == 0) {
        asm volatile("fence.proxy.async.shared::cta;" ::: "memory");
        const uint32_t za = smem_u32(zbuf);
        #pragma unroll
        for (int s = 0; s < 6; ++s) {
            asm volatile(
                "cp.async.bulk.global.shared::cta.bulk_group [%0], [%1], %2;"
                :: "l"((char*)slab + (size_t)s * ZBYTES), "r"(za), "r"(ZBYTES)
                : "memory");
        }
        asm volatile("cp.async.bulk.commit_group;" ::: "memory");
        asm volatile("cp.async.bulk.wait_group 0;" ::: "memory");
    }
    __syncthreads();   // zeros committed & visible before any RED below

    // Accumulate: work item = (entry, feature), spread over all 256 threads.
    const int cnt   = nOut + nIn + 2;
    const int total = cnt * NFEAT;
    for (int it = tid; it < total; it += 256) {
        const int en = it / NFEAT;
        const int f  = it - en * NFEAT;
        const int e  = sEid[en];
        const float* __restrict__ src =
            (e >= 0) ? (hop + (size_t)e * NFEAT) : (ons + (size_t)ai * NFEAT);
        const float v = cFACS[f] * src[f] * sPh[en];
        int ro = cROWS[f], co = cCOLS[f];
        if (sTr[en]) { const int t = ro; ro = co; co = t; }
        atomicAdd(slab + (size_t)ro * ALLN + sCol[en] + co, v);
    }
}

// ---- complex64 fallback path (kept for safety; unused for f32 output) ----
__global__ __launch_bounds__(256, 8) void hr2hk_scatter_cplx(
    const float* __restrict__ hop,
    const float* __restrict__ ons,
    const float* __restrict__ kpts,
    const int*   __restrict__ eidx,
    const int*   __restrict__ eshift,
    float*       __restrict__ out)
{
    const int w = blockIdx.x;
    const int t = threadIdx.x;
    if (t >= NFEAT * NKP) return;
    const int f = t >> 2;
    const int k = t & 3;
    const bool is_edge = (w < NEDGES);

    int ai, aj;
    float pre, pim;
    if (is_edge) {
        ai = eidx[w];
        aj = eidx[NEDGES + w];
        const float d = kpts[k * 3 + 0] * (float)eshift[w * 3 + 0]
                      + kpts[k * 3 + 1] * (float)eshift[w * 3 + 1]
                      + kpts[k * 3 + 2] * (float)eshift[w * 3 + 2];
        float s, c;
        __sincosf(TWO_PI * d, &s, &c);
        pre = c; pim = -s;
    } else {
        ai = w - NEDGES; aj = ai; pre = 1.f; pim = 0.f;
    }
    if ((unsigned)ai >= NATOMS || (unsigned)aj >= NATOMS) return;

    const float* __restrict__ src =
        is_edge ? (hop + (size_t)w * NFEAT)
                : (ons + (size_t)(w - NEDGES) * NFEAT);
    const float val = cFACS[f] * src[f];
    const float re = val * pre, im = val * pim;
    const int r = ai * NORB + (int)cROWS[f];
    const int c = aj * NORB + (int)cCOLS[f];
    const size_t kbase = (size_t)k * ALLN * ALLN;
    float* p0 = out + 2 * (kbase + (size_t)r * ALLN + c);
    float* p1 = out + 2 * (kbase + (size_t)c * ALLN + r);
    atomicAdd(p0 + 0, re);
    atomicAdd(p0 + 1, im);
    atomicAdd(p1 + 0, re);
    atomicAdd(p1 + 1, -im);
}

__global__ void hr2hk_zero(uint4* __restrict__ out, size_t n_u4) {
    for (size_t i = (size_t)blockIdx.x * blockDim.x + threadIdx.x;
         i < n_u4; i += (size_t)gridDim.x * blockDim.x)
        out[i] = make_uint4(0u, 0u, 0u, 0u);
}

extern "C" void kernel_launch(void* const* d_in, const int* in_sizes, int n_in,
                              void* d_out, int out_size) {
    // Identify inputs by (pairwise-distinct) element counts, not position.
    const float* hop    = nullptr;
    const float* ons    = nullptr;
    const float* kpts   = nullptr;
    const int*   eidx   = nullptr;
    const int*   eshift = nullptr;

    for (int i = 0; i < n_in; ++i) {
        switch (in_sizes[i]) {
            case NEDGES * NFEAT: hop    = (const float*)d_in[i]; break;  // 356352
            case NATOMS * NFEAT: ons    = (const float*)d_in[i]; break;  // 22272
            case NKP * 3:        kpts   = (const float*)d_in[i]; break;  // 12
            case 2 * NEDGES:     eidx   = (const int*)d_in[i];   break;  // 12288
            case NEDGES * 3:     eshift = (const int*)d_in[i];   break;  // 18432
            default: break;
        }
    }
    if (!hop || !ons || !kpts || !eidx || !eshift) return;

    if ((long long)out_size == (long long)NCPLX) {
        // float32 real-part output: bucket prepass + fused fill/accumulate.
        prep_zero<<<3, 256>>>();
        prep_fill<<<(NEDGES + 255) / 256, 256>>>(eidx);
        hr2hk_fused<<<NATOMS * NKP, 256>>>(
            hop, ons, kpts, eidx, eshift, (float*)d_out);
    } else if ((long long)out_size == 2LL * (long long)NCPLX) {
        hr2hk_zero<<<8192, 256>>>((uint4*)d_out, NCPLX * 8 / 16);
        hr2hk_scatter_cplx<<<NEDGES + NATOMS, 256>>>(
            hop, ons, kpts, eidx, eshift, (float*)d_out);
    }
}